// round 6
// baseline (speedup 1.0000x reference)
#include <cuda_runtime.h>

#define NB 64
#define NN 1024
#define NWORDS 32          // NN/32 bitmask words per node row
#define NITER 5

// scratch (no allocations allowed)
__device__ float g_feats[NB * NN];   // per-graph label histograms (6 stages)
__device__ float g_dnorm[NB];        // sqrt(dot(feats_b, feats_b))

// compare-exchange
__device__ __forceinline__ unsigned cex(unsigned a, unsigned b, bool keep_min)
{
    unsigned mn = a < b ? a : b;
    unsigned mx = a < b ? b : a;
    return keep_min ? mn : mx;
}

// one bitonic stage (merge size k, distance j) evaluated at position t
__device__ __forceinline__ unsigned stage_single(const unsigned* in, int t, int k, int j)
{
    bool asc = ((t & k) == 0);
    return cex(in[t], in[t ^ j], (((t & j) == 0) == asc));
}

// two consecutive stages (j1 then j2=j1/2) fused: 4 reads, 3 cex.
__device__ __forceinline__ unsigned stage_pair(const unsigned* in, int t, int k, int j1, int j2)
{
    bool asc = ((t & k) == 0);
    unsigned x0 = in[t];
    unsigned x1 = in[t ^ j1];
    unsigned y0 = in[t ^ j2];
    unsigned y1 = in[(t ^ j2) ^ j1];
    bool km1 = (((t & j1) == 0) == asc);
    unsigned a  = cex(x0, x1, km1);
    unsigned bb = cex(y0, y1, km1);
    return cex(a, bb, (((t & j2) == 0) == asc));
}

// intra-warp bitonic merge on 32-bit keys: j = jstart..1 via shuffles
__device__ __forceinline__ unsigned warp_merge32(unsigned v, int t, int k, int jstart)
{
    bool dir = ((t & k) == 0);
    #pragma unroll
    for (int j = jstart; j > 0; j >>= 1) {
        unsigned o = __shfl_xor_sync(0xffffffffu, v, j);
        bool keep_min = (((t & j) == 0) == dir);
        unsigned mn = v < o ? v : o;
        unsigned mx = v < o ? o : v;
        v = keep_min ? mn : mx;
    }
    return v;
}

// -------------------------------------------------------------------------
// Kernel 1: one block per graph.
// Dynamic SMEM (217088 B, opt-in):
//   [0      , 131072) : unsigned smask[32768]   adjacency bits (build only)
//   [131072 , 196608) : u16 s_ent[32768]        CSR entries (even-aligned runs)
//   [196608 , 200704) : int s_lab[1024]         labels
//   [200704 , 204800) : int s_cnt[1024]         histogram counts
//   [204800 , 208896) : unsigned s_keyA[1024]   sort ping buffer
//   [208896 , 212992) : unsigned s_keyB[1024]   sort pong buffer (also run-pos)
//   [212992 , 217088) : int s_scan[1024]        rank per sorted position
// -------------------------------------------------------------------------
extern "C" __global__ void __launch_bounds__(1024, 1)
wl_kernel(const int* __restrict__ esrc, const int* __restrict__ edst,
          const int* __restrict__ labels0, const float* __restrict__ hw, int E)
{
    extern __shared__ unsigned char s_raw[];
    unsigned*       smask  = (unsigned*)s_raw;                  // 128KB
    unsigned short* s_ent  = (unsigned short*)(s_raw + 131072); // 64KB
    int*            s_lab  = (int*)(s_raw + 196608);            // 4KB
    int*            s_cnt  = (int*)(s_raw + 200704);            // 4KB
    unsigned*       s_keyA = (unsigned*)(s_raw + 204800);       // 4KB
    unsigned*       s_keyB = (unsigned*)(s_raw + 208896);       // 4KB
    int*            s_scan = (int*)(s_raw + 212992);            // 4KB
    __shared__ int s_warp[32];

    const int t    = threadIdx.x;
    const int b    = blockIdx.x;
    const int lane = t & 31;
    const int wid  = t >> 5;
    const float w0 = hw[0], w1 = hw[1];

    // --- zero mask + counts ---
    #pragma unroll
    for (int w = 0; w < NWORDS; w++) smask[t + w * 1024] = 0u;
    s_cnt[t] = 0;
    __syncthreads();

    // --- build directed adjacency bitmask (atomicOr dedupes edges) ---
    if ((E & 3) == 0) {
        const int4* s4 = (const int4*)(esrc + (size_t)b * E);
        const int4* d4 = (const int4*)(edst + (size_t)b * E);
        const int n4 = E >> 2;
        for (int i = t; i < n4; i += 1024) {
            int4 s = s4[i];
            int4 d = d4[i];
            atomicOr(&smask[(s.x << 5) + (d.x >> 5)], 1u << (d.x & 31));
            atomicOr(&smask[(s.y << 5) + (d.y >> 5)], 1u << (d.y & 31));
            atomicOr(&smask[(s.z << 5) + (d.z >> 5)], 1u << (d.z & 31));
            atomicOr(&smask[(s.w << 5) + (d.w >> 5)], 1u << (d.w & 31));
        }
    } else {
        for (int e = t; e < E; e += 1024) {
            int s = esrc[b * E + e];
            int d = edst[b * E + e];
            atomicOr(&smask[(s << 5) + (d >> 5)], 1u << (d & 31));
        }
    }

    // --- initial labels + histogram stage 0 (one-time atomics, 16 bins) ---
    int mylab = labels0[b * NN + t];
    s_lab[t] = mylab;
    atomicAdd(&s_cnt[mylab], 1);
    __syncthreads();

    // --- degree (staggered word order -> conflict-free LDS) ---
    int deg = 0;
    #pragma unroll
    for (int wi = 0; wi < NWORDS; wi++) {
        int w = (wi + t) & 31;
        deg += __popc(smask[(t << 5) + w]);
    }
    const int degPad = (deg + 1) & ~1;     // even-align each node's CSR run

    // --- K = max degree, exclusive scan of degPad -> even CSR offsets ---
    int kv = deg;
    #pragma unroll
    for (int o = 16; o > 0; o >>= 1) kv = max(kv, __shfl_xor_sync(0xffffffffu, kv, o));
    int incl = degPad;
    #pragma unroll
    for (int o = 1; o < 32; o <<= 1) {
        int n = __shfl_up_sync(0xffffffffu, incl, o);
        if (lane >= o) incl += n;
    }
    if (lane == 31) { s_warp[wid] = incl; s_scan[wid] = kv; }
    __syncthreads();
    if (t < 32) {
        int x = s_warp[t];
        #pragma unroll
        for (int o = 1; o < 32; o <<= 1) {
            int n = __shfl_up_sync(0xffffffffu, x, o);
            if (t >= o) x += n;
        }
        s_warp[t] = x;
        int m = s_scan[t];
        #pragma unroll
        for (int o = 16; o > 0; o >>= 1) m = max(m, __shfl_xor_sync(0xffffffffu, m, o));
        if (t == 0) s_scan[0] = m;
    }
    __syncthreads();
    const int K   = s_scan[0];
    const int off = (wid > 0 ? s_warp[wid - 1] : 0) + incl - degPad;  // even
    __syncthreads();

    // --- build CSR u16 neighbor entries (once) ---
    {
        int p = off;
        #pragma unroll
        for (int w = 0; w < NWORDS; w++) {
            unsigned m = smask[(t << 5) + w];
            int base = w << 5;
            while (m) {
                int bb = __ffs(m) - 1;
                m &= m - 1;
                s_ent[p++] = (unsigned short)(base + bb);
            }
        }
    }
    __syncthreads();

    const float Kw0 = __fmul_rn((float)K, w0);
    const unsigned* e32base = (const unsigned*)s_ent;

    for (int it = 0; it < NITER; it++) {
        // --- seg = sum of neighbor labels; u32-packed reads (2 entries/LDS) ---
        int seg = 0;
        {
            const unsigned* e32 = e32base + (off >> 1);
            const int nf = deg >> 1;
            #pragma unroll 4
            for (int n = 0; n < nf; n++) {
                unsigned e = e32[n];
                seg += s_lab[e & 0xFFFFu] + s_lab[e >> 16];
            }
            if (deg & 1) seg += s_lab[s_ent[off + deg - 1]];
        }

        // --- hashed = (K*w0)*lab + w1*(seg+deg-K), no FMA contraction ---
        float h = __fadd_rn(__fmul_rn(Kw0, (float)mylab),
                            __fmul_rn(w1, (float)(seg + deg - K)));
        h = __fadd_rn(h, 0.0f);               // canonicalize -0 -> +0
        unsigned u = __float_as_uint(h);
        u = (u & 0x80000000u) ? ~u : (u | 0x80000000u);   // order-preserving map
        const unsigned mykey = u;
        unsigned v = u;

        // --- warp phase: k = 2..32 in registers ---
        #pragma unroll
        for (int k = 2; k <= 32; k <<= 1)
            v = warp_merge32(v, t, k, k >> 1);

        unsigned* cur = s_keyA;
        unsigned* nxt = s_keyB;
        cur[t] = v;
        __syncthreads();

        // --- k=64 ---
        v = stage_single(cur, t, 64, 32);
        v = warp_merge32(v, t, 64, 16);
        nxt[t] = v; { unsigned* tmp = cur; cur = nxt; nxt = tmp; }
        __syncthreads();

        // --- k=128 ---
        v = stage_pair(cur, t, 128, 64, 32);
        v = warp_merge32(v, t, 128, 16);
        nxt[t] = v; { unsigned* tmp = cur; cur = nxt; nxt = tmp; }
        __syncthreads();

        // --- k=256 ---
        v = stage_pair(cur, t, 256, 128, 64);
        nxt[t] = v; { unsigned* tmp = cur; cur = nxt; nxt = tmp; }
        __syncthreads();
        v = stage_single(cur, t, 256, 32);
        v = warp_merge32(v, t, 256, 16);
        nxt[t] = v; { unsigned* tmp = cur; cur = nxt; nxt = tmp; }
        __syncthreads();

        // --- k=512 ---
        v = stage_pair(cur, t, 512, 256, 128);
        nxt[t] = v; { unsigned* tmp = cur; cur = nxt; nxt = tmp; }
        __syncthreads();
        v = stage_pair(cur, t, 512, 64, 32);
        v = warp_merge32(v, t, 512, 16);
        nxt[t] = v; { unsigned* tmp = cur; cur = nxt; nxt = tmp; }
        __syncthreads();

        // --- k=1024 ---
        v = stage_pair(cur, t, 1024, 512, 256);
        nxt[t] = v; { unsigned* tmp = cur; cur = nxt; nxt = tmp; }
        __syncthreads();
        v = stage_pair(cur, t, 1024, 128, 64);
        nxt[t] = v; { unsigned* tmp = cur; cur = nxt; nxt = tmp; }
        __syncthreads();
        v = stage_single(cur, t, 1024, 32);
        v = warp_merge32(v, t, 1024, 16);
        nxt[t] = v; { unsigned* tmp = cur; cur = nxt; nxt = tmp; }
        __syncthreads();
        // cur[] fully sorted; nxt[] free; v = cur[t]

        // --- rank per sorted position: boundary flag + block scan ---
        int flag = 0;
        if (t > 0) flag = (v != cur[t - 1]) ? 1 : 0;
        int val = flag;
        #pragma unroll
        for (int o = 1; o < 32; o <<= 1) {
            int n = __shfl_up_sync(0xffffffffu, val, o);
            if (lane >= o) val += n;
        }
        if (lane == 31) s_warp[wid] = val;
        __syncthreads();
        if (t < 32) {
            int x = s_warp[t];
            #pragma unroll
            for (int o = 1; o < 32; o <<= 1) {
                int n = __shfl_up_sync(0xffffffffu, x, o);
                if (t >= o) x += n;
            }
            s_warp[t] = x;
        }
        __syncthreads();
        const int rank_p = val + (wid > 0 ? s_warp[wid - 1] : 0);
        int* s_pos = (int*)nxt;           // reuse free pong buffer
        s_scan[t] = rank_p;
        s_pos[t]  = 1024;                 // sentinel
        __syncthreads();

        const bool isstart = (t == 0) | (flag != 0);
        if (isstart) s_pos[rank_p] = t;
        __syncthreads();

        // --- atomic-free histogram: run-length = next start - my start ---
        if (isstart) {
            int end = (rank_p == 1023) ? 1024 : s_pos[rank_p + 1];
            s_cnt[rank_p] += end - t;
        }

        // --- binary-search my key (pow-2 lower_bound, barrier-free) ---
        int lo = 0;
        #pragma unroll
        for (int s = 512; s > 0; s >>= 1)
            if (cur[lo + s - 1] < mykey) lo += s;

        int rank = s_scan[lo];
        s_lab[t] = rank;
        mylab    = rank;
        __syncthreads();
    }

    // --- feats + norm ---
    float c = (float)s_cnt[t];
    g_feats[b * NN + t] = c;

    float sq = c * c;
    #pragma unroll
    for (int o = 16; o > 0; o >>= 1) sq += __shfl_xor_sync(0xffffffffu, sq, o);
    if (lane == 0) s_warp[wid] = __float_as_int(sq);
    __syncthreads();
    if (t < 32) {
        float x = __int_as_float(s_warp[t]);
        #pragma unroll
        for (int o = 16; o > 0; o >>= 1) x += __shfl_xor_sync(0xffffffffu, x, o);
        if (t == 0) g_dnorm[b] = sqrtf(x);
    }
}

// -------------------------------------------------------------------------
// Kernel 2: tiled normalized Gram. Grid (8,8), 256 threads. Block (bi,bj):
// 8 rows of A and 8 rows of B in SMEM (64KB); warp w computes 8 dots with
// its A-row cached in registers.
// -------------------------------------------------------------------------
extern "C" __global__ void __launch_bounds__(256)
gram_kernel(float* __restrict__ out)
{
    extern __shared__ float sAB[];            // 2 * 8 * 1024 floats = 64KB
    float4* sA4 = (float4*)sAB;               // 2048 float4
    float4* sB4 = (float4*)(sAB + 8 * NN);    // 2048 float4
    const int bi = blockIdx.x, bj = blockIdx.y;
    const int t  = threadIdx.x;

    const float4* gA = (const float4*)&g_feats[bi * 8 * NN];
    const float4* gB = (const float4*)&g_feats[bj * 8 * NN];
    #pragma unroll
    for (int i = t; i < 2048; i += 256) { sA4[i] = gA[i]; sB4[i] = gB[i]; }
    __syncthreads();

    const int w = t >> 5, lane = t & 31;
    float4 av[8];
    #pragma unroll
    for (int m = 0; m < 8; m++) av[m] = sA4[w * 256 + lane + m * 32];
    const float dn_i = g_dnorm[bi * 8 + w];

    #pragma unroll
    for (int jj = 0; jj < 8; jj++) {
        float s = 0.0f;
        #pragma unroll
        for (int m = 0; m < 8; m++) {
            float4 bv = sB4[jj * 256 + lane + m * 32];
            s += av[m].x * bv.x + av[m].y * bv.y + av[m].z * bv.z + av[m].w * bv.w;
        }
        #pragma unroll
        for (int o = 16; o > 0; o >>= 1) s += __shfl_xor_sync(0xffffffffu, s, o);
        if (lane == 0)
            out[(bi * 8 + w) * NB + bj * 8 + jj] = s / (dn_i * g_dnorm[bj * 8 + jj]);
    }
}

extern "C" void kernel_launch(void* const* d_in, const int* in_sizes, int n_in,
                              void* d_out, int out_size)
{
    const int*   esrc = (const int*)d_in[0];
    const int*   edst = (const int*)d_in[1];
    const int*   lab  = (const int*)d_in[2];
    const float* hw   = (const float*)d_in[3];
    const int E = in_sizes[0] / NB;

    const size_t smem_wl   = 217088;  // 128K mask + 64K ent + 5x4K arrays
    const size_t smem_gram = 65536;
    static bool attr_done = false;
    if (!attr_done) {
        cudaFuncSetAttribute(wl_kernel, cudaFuncAttributeMaxDynamicSharedMemorySize,
                             (int)smem_wl);
        cudaFuncSetAttribute(gram_kernel, cudaFuncAttributeMaxDynamicSharedMemorySize,
                             (int)smem_gram);
        attr_done = true;
    }
    wl_kernel<<<NB, 1024, smem_wl>>>(esrc, edst, lab, hw, E);
    gram_kernel<<<dim3(8, 8), 256, smem_gram>>>((float*)d_out);
}